// round 1
// baseline (speedup 1.0000x reference)
#include <cuda_runtime.h>
#include <cuda_bf16.h>
#include <math.h>

#define Bsz 16
#define Lsz 4096
#define Hsz 128
#define N2 32
#define NL 4
#define O2 256
#define DOUT 100
#define Q 128
#define NC (Lsz / Q)   // 32

typedef unsigned long long u64;

// ---------------- f32x2 packed helpers ----------------
__device__ __forceinline__ u64 pk(float a, float b) {
    u64 r; asm("mov.b64 %0,{%1,%2};" : "=l"(r) : "f"(a), "f"(b)); return r;
}
__device__ __forceinline__ float2 upk(u64 v) {
    float2 r; asm("mov.b64 {%0,%1},%2;" : "=f"(r.x), "=f"(r.y) : "l"(v)); return r;
}
__device__ __forceinline__ u64 fma2(u64 a, u64 b, u64 c) {
    u64 r; asm("fma.rn.f32x2 %0,%1,%2,%3;" : "=l"(r) : "l"(a), "l"(b), "l"(c)); return r;
}
__device__ __forceinline__ u64 mul2(u64 a, u64 b) {
    u64 r; asm("mul.rn.f32x2 %0,%1,%2;" : "=l"(r) : "l"(a), "l"(b)); return r;
}
__device__ __forceinline__ u64 add2(u64 a, u64 b) {
    u64 r; asm("add.rn.f32x2 %0,%1,%2;" : "=l"(r) : "l"(a), "l"(b)); return r;
}

// ---------------- scratch (device globals; no allocation) ----------------
__device__ float  d_hact[Bsz * Hsz * Lsz];   // activation, layout (B,H,L)
__device__ float  d_ybuf[Bsz * Hsz * Lsz];   // conv partial / pre-LN buffer
__device__ float  d_gbuf[Bsz * Hsz * Lsz];   // gelu output (GEMM input)
__device__ float2 d_wend[Bsz * Hsz * NC * N2];
__device__ float2 d_T[Bsz * Hsz * NC * N2];
__device__ float4 d_rc[NL * Hsz * N2];       // {r.re, r.im, 2Cd.re, 2Cd.im}
__device__ float2 d_rq[NL * Hsz * N2];       // r^Q
__device__ float  d_pool[Bsz * Hsz];

// ---------------- prep: discretize SSM params ----------------
__global__ void prep_kernel(const float* __restrict__ log_dt,
                            const float* __restrict__ Cp,
                            const float* __restrict__ logAre,
                            const float* __restrict__ Aimp) {
    int idx = blockIdx.x * 256 + threadIdx.x;
    if (idx >= NL * Hsz * N2) return;
    int h = (idx >> 5) & 127;
    int layer = idx >> 12;
    float dt  = expf(log_dt[layer * Hsz + h]);
    float Are = -expf(logAre[idx]);
    float Ai  = Aimp[idx];
    float dre = Are * dt, dim = Ai * dt;
    float er  = expf(dre);
    float rre = er * cosf(dim), rim = er * sinf(dim);
    float den = Are * Are + Ai * Ai;
    float nre = rre - 1.0f, nim = rim;
    float fre = (nre * Are + nim * Ai) / den;
    float fim = (nim * Are - nre * Ai) / den;
    float Cre = Cp[idx * 2], Cim = Cp[idx * 2 + 1];
    float cdre = 2.0f * (Cre * fre - Cim * fim);
    float cdim = 2.0f * (Cre * fim + Cim * fre);
    d_rc[idx] = make_float4(rre, rim, cdre, cdim);
    // r^Q by 7 squarings (Q = 128)
    float qr = rre, qi = rim;
#pragma unroll
    for (int i = 0; i < 7; i++) {
        float a = qr * qr - qi * qi;
        float b = 2.0f * qr * qi;
        qr = a; qi = b;
    }
    d_rq[idx] = make_float2(qr, qi);
}

// ---------------- encoder: (B,L,1) -> (B,H,L) ----------------
__global__ void enc_kernel(const float* __restrict__ x,
                           const float* __restrict__ ew,
                           const float* __restrict__ eb) {
    int idx = blockIdx.x * 256 + threadIdx.x;   // over B*H*(L/4)
    if (idx >= Bsz * Hsz * (Lsz / 4)) return;
    int l4 = idx & ((Lsz / 4) - 1);
    int h  = (idx >> 10) & 127;
    int b  = idx >> 17;
    float4 xv = ((const float4*)x)[b * (Lsz / 4) + l4];
    float w = ew[h], bb = eb[h];
    float4 o = make_float4(xv.x * w + bb, xv.y * w + bb, xv.z * w + bb, xv.w * w + bb);
    *(float4*)(d_hact + ((size_t)(b * Hsz + h)) * Lsz + l4 * 4) = o;
}

// ---------------- pass1: chunk-local scan (zero init) ----------------
__global__ void __launch_bounds__(64) pass1_kernel(int layer) {
    int bh = blockIdx.x;           // b*H + h
    int tid = threadIdx.x;         // 64 = 32 chunks x 2 halves
    int chunk = tid >> 1, half = tid & 1;
    int h = bh & 127;

    const float4* rcp = &d_rc[((layer << 7) + h) * N2 + (half << 4)];
    u64 rre[8], rim[8], nri[8], cre[8], cim[8];
#pragma unroll
    for (int k = 0; k < 8; k++) {
        float4 a = rcp[2 * k], c = rcp[2 * k + 1];
        rre[k] = pk(a.x, c.x);
        rim[k] = pk(a.y, c.y);
        nri[k] = pk(-a.y, -c.y);
        cre[k] = pk(a.z, c.z);
        cim[k] = pk(a.w, c.w);
    }
    u64 z = pk(0.0f, 0.0f);
    u64 wre[8], wim[8];
#pragma unroll
    for (int k = 0; k < 8; k++) { wre[k] = z; wim[k] = z; }

    const float* up = d_hact + (size_t)bh * Lsz + chunk * Q;
    float*       yp = d_ybuf + (size_t)bh * Lsz + chunk * Q;

#pragma unroll 2
    for (int j = 0; j < Q; j++) {
        float uu = up[j];
        u64 u2 = pk(uu, uu);
        u64 yacc = z;
#pragma unroll
        for (int k = 0; k < 8; k++) {
            u64 a1 = fma2(wre[k], rre[k], mul2(cre[k], u2));
            u64 nr = fma2(wim[k], nri[k], a1);
            u64 a2 = fma2(wim[k], rre[k], mul2(cim[k], u2));
            wim[k] = fma2(wre[k], rim[k], a2);
            wre[k] = nr;
            yacc = add2(yacc, nr);
        }
        float2 yy = upk(yacc);
        float y = yy.x + yy.y;
        y += __shfl_xor_sync(0xffffffffu, y, 1);
        if (!half) yp[j] = y;
    }

    float2* we = &d_wend[((size_t)bh * NC + chunk) * N2 + (half << 4)];
#pragma unroll
    for (int k = 0; k < 8; k++) {
        float2 a = upk(wre[k]), bI = upk(wim[k]);
        we[2 * k]     = make_float2(a.x, bI.x);
        we[2 * k + 1] = make_float2(a.y, bI.y);
    }
}

// ---------------- carry scan across chunks ----------------
__global__ void carry_kernel(int layer) {
    int idx = blockIdx.x * 256 + threadIdx.x;   // B*H*N2 = 65536
    int n = idx & 31;
    int bh = idx >> 5;
    int h = bh & 127;
    float2 q = d_rq[((layer << 7) + h) * N2 + n];
    float tr = 0.0f, ti = 0.0f;
#pragma unroll
    for (int c = 0; c < NC; c++) {
        size_t o = ((size_t)bh * NC + c) * N2 + n;
        d_T[o] = make_float2(tr, ti);
        float2 e = d_wend[o];
        float a = tr * q.x - ti * q.y + e.x;
        ti = tr * q.y + ti * q.x + e.y;
        tr = a;
    }
}

// ---------------- pass3: carry correction + D*u + GELU ----------------
__global__ void __launch_bounds__(64) pass3_kernel(int layer, const float* __restrict__ Dp) {
    int bh = blockIdx.x;
    int tid = threadIdx.x;
    int chunk = tid >> 1, half = tid & 1;
    int h = bh & 127;

    const float4* rcp = &d_rc[((layer << 7) + h) * N2 + (half << 4)];
    u64 rre[8], rim[8], nri[8];
#pragma unroll
    for (int k = 0; k < 8; k++) {
        float4 a = rcp[2 * k], c = rcp[2 * k + 1];
        rre[k] = pk(a.x, c.x);
        rim[k] = pk(a.y, c.y);
        nri[k] = pk(-a.y, -c.y);
    }
    const float2* Tp = &d_T[((size_t)bh * NC + chunk) * N2 + (half << 4)];
    u64 tre[8], tim[8];
#pragma unroll
    for (int k = 0; k < 8; k++) {
        float2 a = Tp[2 * k], c = Tp[2 * k + 1];
        tre[k] = pk(a.x, c.x);
        tim[k] = pk(a.y, c.y);
    }
    float dh = Dp[(layer << 7) + h];
    const float* up = d_hact + (size_t)bh * Lsz + chunk * Q;
    const float* yp = d_ybuf + (size_t)bh * Lsz + chunk * Q;
    float*       gp = d_gbuf + (size_t)bh * Lsz + chunk * Q;

#pragma unroll 2
    for (int j = 0; j < Q; j++) {
        u64 yacc = pk(0.0f, 0.0f);
#pragma unroll
        for (int k = 0; k < 8; k++) {
            u64 nr = fma2(tim[k], nri[k], mul2(tre[k], rre[k]));
            u64 ni = fma2(tre[k], rim[k], mul2(tim[k], rre[k]));
            tre[k] = nr; tim[k] = ni;
            yacc = add2(yacc, nr);
        }
        float2 yy = upk(yacc);
        float corr = yy.x + yy.y;
        corr += __shfl_xor_sync(0xffffffffu, corr, 1);
        if (!half) {
            float y = yp[j] + corr + dh * up[j];
            float gel = 0.5f * y * (1.0f + erff(y * 0.70710678118654752f));
            gp[j] = gel;
        }
    }
}

// ---------------- GLU GEMM: z = W @ g + b, GLU, + residual ----------------
__global__ void __launch_bounds__(256) glu_kernel(const float* __restrict__ Wp,
                                                  const float* __restrict__ bp,
                                                  int layer) {
    __shared__ float Ws[16][O2];   // 16 KB
    __shared__ float Gs[16][64];   // 4 KB
    int t = threadIdx.x;
    int b = blockIdx.y;
    int l0 = blockIdx.x << 6;
    const float* Wl = Wp + layer * O2 * Hsz;
    int og = t >> 3, lg = t & 7;

    u64 acc[8][4];
    u64 z = pk(0.0f, 0.0f);
#pragma unroll
    for (int q = 0; q < 8; q++)
#pragma unroll
        for (int m = 0; m < 4; m++) acc[q][m] = z;

    int gi = t >> 4, gj = (t & 15) << 2;

    for (int h0 = 0; h0 < Hsz; h0 += 16) {
        const float4* wr = (const float4*)(Wl + t * Hsz + h0);
        float wtmp[16];
        *(float4*)(wtmp + 0)  = wr[0];
        *(float4*)(wtmp + 4)  = wr[1];
        *(float4*)(wtmp + 8)  = wr[2];
        *(float4*)(wtmp + 12) = wr[3];
#pragma unroll
        for (int i = 0; i < 16; i++) Ws[i][t] = wtmp[i];

        float4 gv = *(const float4*)(d_gbuf + ((size_t)(b * Hsz + h0 + gi)) * Lsz + l0 + gj);
        *(float4*)&Gs[gi][gj] = gv;
        __syncthreads();

#pragma unroll
        for (int kk = 0; kk < 16; kk++) {
            u64 gv2[4];
#pragma unroll
            for (int m = 0; m < 4; m++)
                gv2[m] = *(const u64*)&Gs[kk][(lg << 3) + (m << 1)];
#pragma unroll
            for (int q = 0; q < 8; q++) {
                int o = (og << 2) + (q & 3) + ((q >> 2) << 7);
                float wv = Ws[kk][o];
                u64 wb = pk(wv, wv);
#pragma unroll
                for (int m = 0; m < 4; m++) acc[q][m] = fma2(wb, gv2[m], acc[q][m]);
            }
        }
        __syncthreads();
    }

    const float* bl = bp + layer * O2;
#pragma unroll
    for (int q = 0; q < 4; q++) {
        int oa = (og << 2) + q;
        int ob = oa + 128;
        float ba = bl[oa], bg = bl[ob];
        size_t rowa = ((size_t)(b * Hsz) + oa) * Lsz + l0 + (lg << 3);
        float4 r0 = *(const float4*)(d_hact + rowa);
        float4 r1 = *(const float4*)(d_hact + rowa + 4);
        float out8[8];
#pragma unroll
        for (int m = 0; m < 4; m++) {
            float2 a  = upk(acc[q][m]);
            float2 g2 = upk(acc[q + 4][m]);
            float z0 = a.x + ba, z1 = a.y + ba;
            float s0 = g2.x + bg, s1 = g2.y + bg;
            s0 = 1.0f / (1.0f + expf(-s0));
            s1 = 1.0f / (1.0f + expf(-s1));
            out8[2 * m]     = z0 * s0;
            out8[2 * m + 1] = z1 * s1;
        }
        out8[0] += r0.x; out8[1] += r0.y; out8[2] += r0.z; out8[3] += r0.w;
        out8[4] += r1.x; out8[5] += r1.y; out8[6] += r1.z; out8[7] += r1.w;
        *(float4*)(d_ybuf + rowa)     = make_float4(out8[0], out8[1], out8[2], out8[3]);
        *(float4*)(d_ybuf + rowa + 4) = make_float4(out8[4], out8[5], out8[6], out8[7]);
    }
}

// ---------------- layernorm over H (per (b,l)) ----------------
__global__ void __launch_bounds__(256) ln_kernel(const float* __restrict__ gp,
                                                 const float* __restrict__ bp,
                                                 int layer) {
    __shared__ float s[Hsz * 65];   // padded to avoid bank conflicts
    __shared__ float mu[64], rsd[64];
    int t = threadIdx.x;
    int b = blockIdx.y;
    int l0 = blockIdx.x << 6;

    for (int i = t; i < 2048; i += 256) {
        int hh = i >> 4, jj = (i & 15) << 2;
        float4 v = *(const float4*)(d_ybuf + ((size_t)(b * Hsz + hh)) * Lsz + l0 + jj);
        float* sp = &s[hh * 65 + jj];
        sp[0] = v.x; sp[1] = v.y; sp[2] = v.z; sp[3] = v.w;
    }
    __syncthreads();
    if (t < 64) {
        float sm = 0.0f;
#pragma unroll 8
        for (int hh = 0; hh < Hsz; hh++) sm += s[hh * 65 + t];
        float m = sm * (1.0f / 128.0f);
        float vq = 0.0f;
#pragma unroll 8
        for (int hh = 0; hh < Hsz; hh++) {
            float d = s[hh * 65 + t] - m;
            vq += d * d;
        }
        mu[t] = m;
        rsd[t] = rsqrtf(vq * (1.0f / 128.0f) + 1e-5f);
    }
    __syncthreads();
    for (int i = t; i < 2048; i += 256) {
        int hh = i >> 4, jj = (i & 15) << 2;
        float g = gp[(layer << 7) + hh], bb = bp[(layer << 7) + hh];
        float* sp = &s[hh * 65 + jj];
        float4 o;
        o.x = (sp[0] - mu[jj])     * rsd[jj]     * g + bb;
        o.y = (sp[1] - mu[jj + 1]) * rsd[jj + 1] * g + bb;
        o.z = (sp[2] - mu[jj + 2]) * rsd[jj + 2] * g + bb;
        o.w = (sp[3] - mu[jj + 3]) * rsd[jj + 3] * g + bb;
        *(float4*)(d_hact + ((size_t)(b * Hsz + hh)) * Lsz + l0 + jj) = o;
    }
}

// ---------------- mean pool over L ----------------
__global__ void pool_kernel() {
    int bh = blockIdx.x;
    int t = threadIdx.x;   // 128
    const float4* p = (const float4*)(d_hact + (size_t)bh * Lsz);
    float sm = 0.0f;
    for (int i = t; i < Lsz / 4; i += 128) {
        float4 v = p[i];
        sm += v.x + v.y + v.z + v.w;
    }
#pragma unroll
    for (int o = 16; o; o >>= 1) sm += __shfl_xor_sync(0xffffffffu, sm, o);
    __shared__ float sh[4];
    if ((t & 31) == 0) sh[t >> 5] = sm;
    __syncthreads();
    if (t == 0) d_pool[bh] = (sh[0] + sh[1] + sh[2] + sh[3]) * (1.0f / Lsz);
}

// ---------------- decoder ----------------
__global__ void dec_kernel(const float* __restrict__ dw,
                           const float* __restrict__ db,
                           float* __restrict__ out) {
    int b = blockIdx.x;
    int t = threadIdx.x;   // 128
    __shared__ float sp[Hsz];
    sp[t] = d_pool[b * Hsz + t];
    __syncthreads();
    if (t < DOUT) {
        float acc = db[t];
#pragma unroll 8
        for (int h = 0; h < Hsz; h++) acc += sp[h] * dw[t * Hsz + h];
        out[b * DOUT + t] = acc;
    }
}

// ---------------- launch ----------------
extern "C" void kernel_launch(void* const* d_in, const int* in_sizes, int n_in,
                              void* d_out, int out_size) {
    const float* x      = (const float*)d_in[0];
    const float* enc_w  = (const float*)d_in[1];
    const float* enc_b  = (const float*)d_in[2];
    const float* log_dt = (const float*)d_in[3];
    const float* Cp     = (const float*)d_in[4];
    const float* logAre = (const float*)d_in[5];
    const float* Aim    = (const float*)d_in[6];
    const float* Dp     = (const float*)d_in[7];
    const float* out_w  = (const float*)d_in[8];
    const float* out_b  = (const float*)d_in[9];
    const float* ln_g   = (const float*)d_in[10];
    const float* ln_b   = (const float*)d_in[11];
    const float* dec_w  = (const float*)d_in[12];
    const float* dec_b  = (const float*)d_in[13];
    float* out = (float*)d_out;

    prep_kernel<<<64, 256>>>(log_dt, Cp, logAre, Aim);
    enc_kernel<<<(Bsz * Hsz * (Lsz / 4) + 255) / 256, 256>>>(x, enc_w, enc_b);

    for (int layer = 0; layer < NL; layer++) {
        pass1_kernel<<<Bsz * Hsz, 64>>>(layer);
        carry_kernel<<<(Bsz * Hsz * N2) / 256, 256>>>(layer);
        pass3_kernel<<<Bsz * Hsz, 64>>>(layer, Dp);
        glu_kernel<<<dim3(Lsz / 64, Bsz), 256>>>(out_w, out_b, layer);
        ln_kernel<<<dim3(Lsz / 64, Bsz), 256>>>(ln_g, ln_b, layer);
    }

    pool_kernel<<<Bsz * Hsz, 128>>>();
    dec_kernel<<<Bsz, 128>>>(dec_w, dec_b, out);
}

// round 2
// speedup vs baseline: 1.2939x; 1.2939x over previous
#include <cuda_runtime.h>
#include <cuda_bf16.h>
#include <math.h>

#define Bsz 16
#define Lsz 4096
#define Hsz 128
#define N2 32
#define NL 4
#define O2 256
#define DOUT 100
#define Q 128
#define NC (Lsz / Q)   // 32

typedef unsigned long long u64;

// ---------------- f32x2 packed helpers ----------------
__device__ __forceinline__ u64 pk(float a, float b) {
    u64 r; asm("mov.b64 %0,{%1,%2};" : "=l"(r) : "f"(a), "f"(b)); return r;
}
__device__ __forceinline__ float2 upk(u64 v) {
    float2 r; asm("mov.b64 {%0,%1},%2;" : "=f"(r.x), "=f"(r.y) : "l"(v)); return r;
}
__device__ __forceinline__ u64 fma2(u64 a, u64 b, u64 c) {
    u64 r; asm("fma.rn.f32x2 %0,%1,%2,%3;" : "=l"(r) : "l"(a), "l"(b), "l"(c)); return r;
}
__device__ __forceinline__ u64 mul2(u64 a, u64 b) {
    u64 r; asm("mul.rn.f32x2 %0,%1,%2;" : "=l"(r) : "l"(a), "l"(b)); return r;
}
__device__ __forceinline__ u64 add2(u64 a, u64 b) {
    u64 r; asm("add.rn.f32x2 %0,%1,%2;" : "=l"(r) : "l"(a), "l"(b)); return r;
}

// ---------------- scratch (device globals; no allocation) ----------------
__device__ float  d_hact[Bsz * Hsz * Lsz];   // activation, layout (B,H,L)
__device__ float  d_gbuf[Bsz * Hsz * Lsz];   // gelu output (GEMM input)
__device__ float4 d_rc[NL * Hsz * N2];       // {r.re, r.im, 2Cd.re, 2Cd.im}
__device__ float2 d_rq[NL * Hsz * N2];       // r^Q
__device__ float  d_pool[Bsz * Hsz];

// ---------------- prep: discretize SSM params ----------------
__global__ void prep_kernel(const float* __restrict__ log_dt,
                            const float* __restrict__ Cp,
                            const float* __restrict__ logAre,
                            const float* __restrict__ Aimp) {
    int idx = blockIdx.x * 256 + threadIdx.x;
    if (idx >= NL * Hsz * N2) return;
    int h = (idx >> 5) & 127;
    int layer = idx >> 12;
    float dt  = expf(log_dt[layer * Hsz + h]);
    float Are = -expf(logAre[idx]);
    float Ai  = Aimp[idx];
    float dre = Are * dt, dim = Ai * dt;
    float er  = expf(dre);
    float rre = er * cosf(dim), rim = er * sinf(dim);
    float den = Are * Are + Ai * Ai;
    float nre = rre - 1.0f, nim = rim;
    float fre = (nre * Are + nim * Ai) / den;
    float fim = (nim * Are - nre * Ai) / den;
    float Cre = Cp[idx * 2], Cim = Cp[idx * 2 + 1];
    float cdre = 2.0f * (Cre * fre - Cim * fim);
    float cdim = 2.0f * (Cre * fim + Cim * fre);
    d_rc[idx] = make_float4(rre, rim, cdre, cdim);
    // r^Q by 7 squarings (Q = 128)
    float qr = rre, qi = rim;
#pragma unroll
    for (int i = 0; i < 7; i++) {
        float a = qr * qr - qi * qi;
        float b = 2.0f * qr * qi;
        qr = a; qi = b;
    }
    d_rq[idx] = make_float2(qr, qi);
}

// ---------------- encoder: (B,L,1) -> (B,H,L) ----------------
__global__ void enc_kernel(const float* __restrict__ x,
                           const float* __restrict__ ew,
                           const float* __restrict__ eb) {
    int idx = blockIdx.x * 256 + threadIdx.x;   // over B*H*(L/4)
    if (idx >= Bsz * Hsz * (Lsz / 4)) return;
    int l4 = idx & ((Lsz / 4) - 1);
    int h  = (idx >> 10) & 127;
    int b  = idx >> 17;
    float4 xv = ((const float4*)x)[b * (Lsz / 4) + l4];
    float w = ew[h], bb = eb[h];
    float4 o = make_float4(xv.x * w + bb, xv.y * w + bb, xv.z * w + bb, xv.w * w + bb);
    *(float4*)(d_hact + ((size_t)(b * Hsz + h)) * Lsz + l4 * 4) = o;
}

// ---------------- fused scan: chunk scan + carry + rescan + D*u + GELU ----
__global__ void __launch_bounds__(64) scan_kernel(int layer, const float* __restrict__ Dp) {
    __shared__ float2 swT[NC * N2];   // 8KB: wend, then prefix T (in place)
    int bh = blockIdx.x;              // b*H + h
    int tid = threadIdx.x;            // 64 = 32 chunks x 2 halves
    int chunk = tid >> 1, half = tid & 1;
    int h = bh & 127;

    const float4* rcp = &d_rc[((layer << 7) + h) * N2 + (half << 4)];
    u64 rre[8], rim[8], nri[8], cre[8], cim[8];
#pragma unroll
    for (int k = 0; k < 8; k++) {
        float4 a = rcp[2 * k], c = rcp[2 * k + 1];
        rre[k] = pk(a.x, c.x);
        rim[k] = pk(a.y, c.y);
        nri[k] = pk(-a.y, -c.y);
        cre[k] = pk(a.z, c.z);
        cim[k] = pk(a.w, c.w);
    }
    u64 z = pk(0.0f, 0.0f);
    u64 wre[8], wim[8];
#pragma unroll
    for (int k = 0; k < 8; k++) { wre[k] = z; wim[k] = z; }

    const float4* up4 = (const float4*)(d_hact + (size_t)bh * Lsz + chunk * Q);

    // ---- phase A: chunk-local end state (zero init, no y) ----
#pragma unroll 1
    for (int j4 = 0; j4 < Q / 4; j4++) {
        float4 uv = up4[j4];
        float us[4] = {uv.x, uv.y, uv.z, uv.w};
#pragma unroll
        for (int s = 0; s < 4; s++) {
            u64 u2 = pk(us[s], us[s]);
#pragma unroll
            for (int k = 0; k < 8; k++) {
                u64 nr = fma2(wim[k], nri[k], fma2(wre[k], rre[k], mul2(cre[k], u2)));
                wim[k] = fma2(wre[k], rim[k], fma2(wim[k], rre[k], mul2(cim[k], u2)));
                wre[k] = nr;
            }
        }
    }
    {
        float2* we = &swT[chunk * N2 + (half << 4)];
#pragma unroll
        for (int k = 0; k < 8; k++) {
            float2 a = upk(wre[k]), bI = upk(wim[k]);
            we[2 * k]     = make_float2(a.x, bI.x);
            we[2 * k + 1] = make_float2(a.y, bI.y);
        }
    }
    __syncthreads();

    // ---- phase 2: carry scan across chunks (warp 0, lane = mode) ----
    if (tid < 32) {
        float2 q = d_rq[((layer << 7) + h) * N2 + tid];
        float tr = 0.0f, ti = 0.0f;
#pragma unroll
        for (int c = 0; c < NC; c++) {
            float2 e = swT[c * N2 + tid];
            swT[c * N2 + tid] = make_float2(tr, ti);
            float a = tr * q.x - ti * q.y + e.x;
            ti = tr * q.y + ti * q.x + e.y;
            tr = a;
        }
    }
    __syncthreads();

    // ---- phase B: rescan with carried initial state, emit GELU ----
    {
        const float2* Tp = &swT[chunk * N2 + (half << 4)];
#pragma unroll
        for (int k = 0; k < 8; k++) {
            float2 t0 = Tp[2 * k], t1 = Tp[2 * k + 1];
            wre[k] = pk(t0.x, t1.x);
            wim[k] = pk(t0.y, t1.y);
        }
    }
    float dh = Dp[(layer << 7) + h];
    float* gp = d_gbuf + (size_t)bh * Lsz + chunk * Q;
#pragma unroll 1
    for (int j4 = 0; j4 < Q / 4; j4++) {
        float4 uv = up4[j4];
        float us[4] = {uv.x, uv.y, uv.z, uv.w};
        float ys[4];
#pragma unroll
        for (int s = 0; s < 4; s++) {
            u64 u2 = pk(us[s], us[s]);
            u64 yacc = z;
#pragma unroll
            for (int k = 0; k < 8; k++) {
                u64 nr = fma2(wim[k], nri[k], fma2(wre[k], rre[k], mul2(cre[k], u2)));
                wim[k] = fma2(wre[k], rim[k], fma2(wim[k], rre[k], mul2(cim[k], u2)));
                wre[k] = nr;
                yacc = add2(yacc, nr);
            }
            float2 yy = upk(yacc);
            float y = yy.x + yy.y;
            y += __shfl_xor_sync(0xffffffffu, y, 1);
            y += dh * us[s];
            ys[s] = 0.5f * y * (1.0f + erff(y * 0.70710678118654752f));
        }
        if (!half) *(float4*)(gp + j4 * 4) = make_float4(ys[0], ys[1], ys[2], ys[3]);
    }
}

// ---------------- GLU GEMM + bias + GLU + residual + LayerNorm ----------
__global__ void __launch_bounds__(256) gluln_kernel(const float* __restrict__ Wp,
                                                    const float* __restrict__ bp,
                                                    const float* __restrict__ lgp,
                                                    const float* __restrict__ lbp,
                                                    int layer) {
    __shared__ __align__(16) char smbuf[37376];
    float* Ws   = (float*)smbuf;            // [16][256]  (GEMM phase)
    float* Gs   = (float*)(smbuf + 16384);  // [16][64]   (GEMM phase)
    float* sout = (float*)smbuf;            // [128][72]  (epilogue phase, reuses buffer)
    float* smu  = (float*)(smbuf + 36864);  // [64]
    float* srs  = smu + 64;                 // [64]

    int t = threadIdx.x;
    int b = blockIdx.y;
    int l0 = blockIdx.x << 6;
    const float* Wl = Wp + layer * O2 * Hsz;
    int og = t >> 3, lg = t & 7;

    u64 acc[8][4];
    u64 z = pk(0.0f, 0.0f);
#pragma unroll
    for (int q = 0; q < 8; q++)
#pragma unroll
        for (int m = 0; m < 4; m++) acc[q][m] = z;

    int gi = t >> 4, gj = (t & 15) << 2;

    for (int h0 = 0; h0 < Hsz; h0 += 16) {
        const float4* wr = (const float4*)(Wl + t * Hsz + h0);
        float wtmp[16];
        *(float4*)(wtmp + 0)  = wr[0];
        *(float4*)(wtmp + 4)  = wr[1];
        *(float4*)(wtmp + 8)  = wr[2];
        *(float4*)(wtmp + 12) = wr[3];
#pragma unroll
        for (int i = 0; i < 16; i++) Ws[i * O2 + t] = wtmp[i];

        float4 gv = *(const float4*)(d_gbuf + ((size_t)(b * Hsz + h0 + gi)) * Lsz + l0 + gj);
        *(float4*)&Gs[gi * 64 + gj] = gv;
        __syncthreads();

#pragma unroll
        for (int kk = 0; kk < 16; kk++) {
            u64 gv2[4];
#pragma unroll
            for (int m = 0; m < 4; m++)
                gv2[m] = *(const u64*)&Gs[kk * 64 + (lg << 3) + (m << 1)];
#pragma unroll
            for (int q = 0; q < 8; q++) {
                int o = (og << 2) + (q & 3) + ((q >> 2) << 7);
                float wv = Ws[kk * O2 + o];
                u64 wb = pk(wv, wv);
#pragma unroll
                for (int m = 0; m < 4; m++) acc[q][m] = fma2(wb, gv2[m], acc[q][m]);
            }
        }
        __syncthreads();
    }

    // epilogue: bias + GLU + residual -> sout (reuses GEMM shared buffer)
    const float* bl = bp + layer * O2;
#pragma unroll
    for (int q = 0; q < 4; q++) {
        int oa = (og << 2) + q;
        int ob = oa + 128;
        float ba = bl[oa], bg = bl[ob];
        size_t rowa = ((size_t)(b * Hsz) + oa) * Lsz + l0 + (lg << 3);
        float4 r0 = *(const float4*)(d_hact + rowa);
        float4 r1 = *(const float4*)(d_hact + rowa + 4);
        float out8[8];
#pragma unroll
        for (int m = 0; m < 4; m++) {
            float2 a  = upk(acc[q][m]);
            float2 g2 = upk(acc[q + 4][m]);
            float z0 = a.x + ba, z1 = a.y + ba;
            float s0 = g2.x + bg, s1 = g2.y + bg;
            s0 = 1.0f / (1.0f + expf(-s0));
            s1 = 1.0f / (1.0f + expf(-s1));
            out8[2 * m]     = z0 * s0;
            out8[2 * m + 1] = z1 * s1;
        }
        out8[0] += r0.x; out8[1] += r0.y; out8[2] += r0.z; out8[3] += r0.w;
        out8[4] += r1.x; out8[5] += r1.y; out8[6] += r1.z; out8[7] += r1.w;
        float* sp = &sout[oa * 72 + (lg << 3)];
#pragma unroll
        for (int i = 0; i < 8; i++) sp[i] = out8[i];
    }
    __syncthreads();

    // LayerNorm over channel dim (128) for each of the 64 l's
    if (t < 64) {
        float sm = 0.0f;
#pragma unroll 8
        for (int hh = 0; hh < Hsz; hh++) sm += sout[hh * 72 + t];
        float m = sm * (1.0f / 128.0f);
        float vq = 0.0f;
#pragma unroll 8
        for (int hh = 0; hh < Hsz; hh++) {
            float d = sout[hh * 72 + t] - m;
            vq += d * d;
        }
        smu[t] = m;
        srs[t] = rsqrtf(vq * (1.0f / 128.0f) + 1e-5f);
    }
    __syncthreads();

    for (int i = t; i < 2048; i += 256) {
        int hh = i >> 4, jj = (i & 15) << 2;
        float g = lgp[(layer << 7) + hh], bb = lbp[(layer << 7) + hh];
        const float* sp = &sout[hh * 72 + jj];
        float4 o;
        o.x = (sp[0] - smu[jj])     * srs[jj]     * g + bb;
        o.y = (sp[1] - smu[jj + 1]) * srs[jj + 1] * g + bb;
        o.z = (sp[2] - smu[jj + 2]) * srs[jj + 2] * g + bb;
        o.w = (sp[3] - smu[jj + 3]) * srs[jj + 3] * g + bb;
        *(float4*)(d_hact + ((size_t)(b * Hsz + hh)) * Lsz + l0 + jj) = o;
    }
}

// ---------------- mean pool over L ----------------
__global__ void pool_kernel() {
    int bh = blockIdx.x;
    int t = threadIdx.x;   // 128
    const float4* p = (const float4*)(d_hact + (size_t)bh * Lsz);
    float sm = 0.0f;
    for (int i = t; i < Lsz / 4; i += 128) {
        float4 v = p[i];
        sm += v.x + v.y + v.z + v.w;
    }
#pragma unroll
    for (int o = 16; o; o >>= 1) sm += __shfl_xor_sync(0xffffffffu, sm, o);
    __shared__ float sh[4];
    if ((t & 31) == 0) sh[t >> 5] = sm;
    __syncthreads();
    if (t == 0) d_pool[bh] = (sh[0] + sh[1] + sh[2] + sh[3]) * (1.0f / Lsz);
}

// ---------------- decoder ----------------
__global__ void dec_kernel(const float* __restrict__ dw,
                           const float* __restrict__ db,
                           float* __restrict__ out) {
    int b = blockIdx.x;
    int t = threadIdx.x;   // 128
    __shared__ float sp[Hsz];
    sp[t] = d_pool[b * Hsz + t];
    __syncthreads();
    if (t < DOUT) {
        float acc = db[t];
#pragma unroll 8
        for (int h = 0; h < Hsz; h++) acc += sp[h] * dw[t * Hsz + h];
        out[b * DOUT + t] = acc;
    }
}

// ---------------- launch ----------------
extern "C" void kernel_launch(void* const* d_in, const int* in_sizes, int n_in,
                              void* d_out, int out_size) {
    const float* x      = (const float*)d_in[0];
    const float* enc_w  = (const float*)d_in[1];
    const float* enc_b  = (const float*)d_in[2];
    const float* log_dt = (const float*)d_in[3];
    const float* Cp     = (const float*)d_in[4];
    const float* logAre = (const float*)d_in[5];
    const float* Aim    = (const float*)d_in[6];
    const float* Dp     = (const float*)d_in[7];
    const float* out_w  = (const float*)d_in[8];
    const float* out_b  = (const float*)d_in[9];
    const float* ln_g   = (const float*)d_in[10];
    const float* ln_b   = (const float*)d_in[11];
    const float* dec_w  = (const float*)d_in[12];
    const float* dec_b  = (const float*)d_in[13];
    float* out = (float*)d_out;

    prep_kernel<<<64, 256>>>(log_dt, Cp, logAre, Aim);
    enc_kernel<<<(Bsz * Hsz * (Lsz / 4) + 255) / 256, 256>>>(x, enc_w, enc_b);

    for (int layer = 0; layer < NL; layer++) {
        scan_kernel<<<Bsz * Hsz, 64>>>(layer, Dp);
        gluln_kernel<<<dim3(Lsz / 64, Bsz), 256>>>(out_w, out_b, ln_g, ln_b, layer);
    }

    pool_kernel<<<Bsz * Hsz, 128>>>();
    dec_kernel<<<Bsz, 128>>>(dec_w, dec_b, out);
}

// round 3
// speedup vs baseline: 1.8076x; 1.3970x over previous
#include <cuda_runtime.h>
#include <cuda_bf16.h>
#include <math.h>

#define Bsz 16
#define Lsz 4096
#define Hsz 128
#define N2 32
#define NL 4
#define O2 256
#define DOUT 100
#define Q 128
#define NC (Lsz / Q)   // 32

typedef unsigned long long u64;
typedef unsigned int u32;

// ---------------- f32x2 packed helpers ----------------
__device__ __forceinline__ u64 pk(float a, float b) {
    u64 r; asm("mov.b64 %0,{%1,%2};" : "=l"(r) : "f"(a), "f"(b)); return r;
}
__device__ __forceinline__ float2 upk(u64 v) {
    float2 r; asm("mov.b64 {%0,%1},%2;" : "=f"(r.x), "=f"(r.y) : "l"(v)); return r;
}
__device__ __forceinline__ u64 fma2(u64 a, u64 b, u64 c) {
    u64 r; asm("fma.rn.f32x2 %0,%1,%2,%3;" : "=l"(r) : "l"(a), "l"(b), "l"(c)); return r;
}
__device__ __forceinline__ u64 mul2(u64 a, u64 b) {
    u64 r; asm("mul.rn.f32x2 %0,%1,%2;" : "=l"(r) : "l"(a), "l"(b)); return r;
}
__device__ __forceinline__ u64 add2(u64 a, u64 b) {
    u64 r; asm("add.rn.f32x2 %0,%1,%2;" : "=l"(r) : "l"(a), "l"(b)); return r;
}
__device__ __forceinline__ u32 to_tf32(float x) {
    u32 r; asm("cvt.rna.tf32.f32 %0, %1;" : "=r"(r) : "f"(x)); return r;
}
__device__ __forceinline__ void mma_tf32(float c[4], const u32 a[4], const u32 b[2]) {
    asm volatile("mma.sync.aligned.m16n8k8.row.col.f32.tf32.tf32.f32 "
                 "{%0,%1,%2,%3}, {%4,%5,%6,%7}, {%8,%9}, {%0,%1,%2,%3};"
                 : "+f"(c[0]), "+f"(c[1]), "+f"(c[2]), "+f"(c[3])
                 : "r"(a[0]), "r"(a[1]), "r"(a[2]), "r"(a[3]), "r"(b[0]), "r"(b[1]));
}

// ---------------- scratch (device globals; no allocation) ----------------
__device__ float  d_hact[Bsz * Hsz * Lsz];   // activation, layout (B,H,L)
__device__ float  d_gbuf[Bsz * Hsz * Lsz];   // gelu output (GEMM input)
__device__ float4 d_rc[NL * Hsz * N2];       // {r.re, r.im, 2Cd.re, 2Cd.im}
__device__ float2 d_rq[NL * Hsz * N2];       // r^Q
__device__ float  d_pool[Bsz * Hsz];

// ---------------- prep: discretize SSM params ----------------
__global__ void prep_kernel(const float* __restrict__ log_dt,
                            const float* __restrict__ Cp,
                            const float* __restrict__ logAre,
                            const float* __restrict__ Aimp) {
    int idx = blockIdx.x * 256 + threadIdx.x;
    if (idx >= NL * Hsz * N2) return;
    int h = (idx >> 5) & 127;
    int layer = idx >> 12;
    float dt  = expf(log_dt[layer * Hsz + h]);
    float Are = -expf(logAre[idx]);
    float Ai  = Aimp[idx];
    float dre = Are * dt, dim = Ai * dt;
    float er  = expf(dre);
    float rre = er * cosf(dim), rim = er * sinf(dim);
    float den = Are * Are + Ai * Ai;
    float nre = rre - 1.0f, nim = rim;
    float fre = (nre * Are + nim * Ai) / den;
    float fim = (nim * Are - nre * Ai) / den;
    float Cre = Cp[idx * 2], Cim = Cp[idx * 2 + 1];
    float cdre = 2.0f * (Cre * fre - Cim * fim);
    float cdim = 2.0f * (Cre * fim + Cim * fre);
    d_rc[idx] = make_float4(rre, rim, cdre, cdim);
    float qr = rre, qi = rim;
#pragma unroll
    for (int i = 0; i < 7; i++) {
        float a = qr * qr - qi * qi;
        float b = 2.0f * qr * qi;
        qr = a; qi = b;
    }
    d_rq[idx] = make_float2(qr, qi);
}

// ---------------- encoder: (B,L,1) -> (B,H,L) ----------------
__global__ void enc_kernel(const float* __restrict__ x,
                           const float* __restrict__ ew,
                           const float* __restrict__ eb) {
    int idx = blockIdx.x * 256 + threadIdx.x;
    if (idx >= Bsz * Hsz * (Lsz / 4)) return;
    int l4 = idx & ((Lsz / 4) - 1);
    int h  = (idx >> 10) & 127;
    int b  = idx >> 17;
    float4 xv = ((const float4*)x)[b * (Lsz / 4) + l4];
    float w = ew[h], bb = eb[h];
    float4 o = make_float4(xv.x * w + bb, xv.y * w + bb, xv.z * w + bb, xv.w * w + bb);
    *(float4*)(d_hact + ((size_t)(b * Hsz + h)) * Lsz + l4 * 4) = o;
}

// ---------------- fused scan: chunk scan + carry + rescan + D*u + GELU ----
__global__ void __launch_bounds__(64) scan_kernel(int layer, const float* __restrict__ Dp) {
    __shared__ float2 swT[NC * N2];
    int bh = blockIdx.x;
    int tid = threadIdx.x;
    int chunk = tid >> 1, half = tid & 1;
    int h = bh & 127;

    const float4* rcp = &d_rc[((layer << 7) + h) * N2 + (half << 4)];
    u64 rre[8], rim[8], nri[8], cre[8], cim[8];
#pragma unroll
    for (int k = 0; k < 8; k++) {
        float4 a = rcp[2 * k], c = rcp[2 * k + 1];
        rre[k] = pk(a.x, c.x);
        rim[k] = pk(a.y, c.y);
        nri[k] = pk(-a.y, -c.y);
        cre[k] = pk(a.z, c.z);
        cim[k] = pk(a.w, c.w);
    }
    u64 z = pk(0.0f, 0.0f);
    u64 wre[8], wim[8];
#pragma unroll
    for (int k = 0; k < 8; k++) { wre[k] = z; wim[k] = z; }

    const float4* up4 = (const float4*)(d_hact + (size_t)bh * Lsz + chunk * Q);

#pragma unroll 1
    for (int j4 = 0; j4 < Q / 4; j4++) {
        float4 uv = up4[j4];
        float us[4] = {uv.x, uv.y, uv.z, uv.w};
#pragma unroll
        for (int s = 0; s < 4; s++) {
            u64 u2 = pk(us[s], us[s]);
#pragma unroll
            for (int k = 0; k < 8; k++) {
                u64 nr = fma2(wim[k], nri[k], fma2(wre[k], rre[k], mul2(cre[k], u2)));
                wim[k] = fma2(wre[k], rim[k], fma2(wim[k], rre[k], mul2(cim[k], u2)));
                wre[k] = nr;
            }
        }
    }
    {
        float2* we = &swT[chunk * N2 + (half << 4)];
#pragma unroll
        for (int k = 0; k < 8; k++) {
            float2 a = upk(wre[k]), bI = upk(wim[k]);
            we[2 * k]     = make_float2(a.x, bI.x);
            we[2 * k + 1] = make_float2(a.y, bI.y);
        }
    }
    __syncthreads();

    if (tid < 32) {
        float2 q = d_rq[((layer << 7) + h) * N2 + tid];
        float tr = 0.0f, ti = 0.0f;
#pragma unroll
        for (int c = 0; c < NC; c++) {
            float2 e = swT[c * N2 + tid];
            swT[c * N2 + tid] = make_float2(tr, ti);
            float a = tr * q.x - ti * q.y + e.x;
            ti = tr * q.y + ti * q.x + e.y;
            tr = a;
        }
    }
    __syncthreads();

    {
        const float2* Tp = &swT[chunk * N2 + (half << 4)];
#pragma unroll
        for (int k = 0; k < 8; k++) {
            float2 t0 = Tp[2 * k], t1 = Tp[2 * k + 1];
            wre[k] = pk(t0.x, t1.x);
            wim[k] = pk(t0.y, t1.y);
        }
    }
    float dh = Dp[(layer << 7) + h];
    float* gp = d_gbuf + (size_t)bh * Lsz + chunk * Q;
#pragma unroll 1
    for (int j4 = 0; j4 < Q / 4; j4++) {
        float4 uv = up4[j4];
        float us[4] = {uv.x, uv.y, uv.z, uv.w};
        float ys[4];
#pragma unroll
        for (int s = 0; s < 4; s++) {
            u64 u2 = pk(us[s], us[s]);
            u64 yacc = z;
#pragma unroll
            for (int k = 0; k < 8; k++) {
                u64 nr = fma2(wim[k], nri[k], fma2(wre[k], rre[k], mul2(cre[k], u2)));
                wim[k] = fma2(wre[k], rim[k], fma2(wim[k], rre[k], mul2(cim[k], u2)));
                wre[k] = nr;
                yacc = add2(yacc, nr);
            }
            float2 yy = upk(yacc);
            float y = yy.x + yy.y;
            y += __shfl_xor_sync(0xffffffffu, y, 1);
            y += dh * us[s];
            ys[s] = 0.5f * y * (1.0f + erff(y * 0.70710678118654752f));
        }
        if (!half) *(float4*)(gp + j4 * 4) = make_float4(ys[0], ys[1], ys[2], ys[3]);
    }
}

// ------- GLU GEMM (tf32 mma) + bias + GLU + residual + LayerNorm ---------
// Block: 256 thr (8 warps), Ltile=64, all 256 output rows.
// Warp w: m-frag 0 = rows [16w,16w+16)  (GLU 'a'), m-frag 1 = rows [128+16w, ...) (gate).
#define WPITCH 36
#define GPITCH 72
__global__ void __launch_bounds__(256) gluln_kernel(const float* __restrict__ Wp,
                                                    const float* __restrict__ bp,
                                                    const float* __restrict__ lgp,
                                                    const float* __restrict__ lbp,
                                                    int layer) {
    __shared__ __align__(16) char smbuf[46080];   // Ws[256][36] u32 | Gs[32][72] u32 ; reused as sout[128][72] f32
    __shared__ float smu[64], srs[64];
    u32*   Ws   = (u32*)smbuf;                    // 36864 B
    u32*   Gs   = (u32*)(smbuf + 36864);          // 9216 B
    float* sout = (float*)smbuf;

    int t = threadIdx.x;
    int w = t >> 5;
    int lane = t & 31;
    int grp = lane >> 2, t4 = lane & 3;
    int b = blockIdx.y;
    int l0 = blockIdx.x << 6;
    const float* Wl = Wp + layer * O2 * Hsz;

    float acc[2][8][4];
#pragma unroll
    for (int m = 0; m < 2; m++)
#pragma unroll
        for (int n = 0; n < 8; n++)
#pragma unroll
            for (int i = 0; i < 4; i++) acc[m][n][i] = 0.0f;

    int wo = t >> 3, wk4 = t & 7;      // W staging: o-lane, k4-lane
    int gl4 = t & 15, gk = t >> 4;     // G staging

#pragma unroll 1
    for (int kc = 0; kc < 4; kc++) {
        // stage W[o][k] chunk (256 o x 32 k), tf32-converted
#pragma unroll
        for (int r = 0; r < 8; r++) {
            int o = r * 32 + wo;
            float4 v = *(const float4*)(Wl + o * Hsz + kc * 32 + wk4 * 4);
            u32* d = &Ws[o * WPITCH + wk4 * 4];
            d[0] = to_tf32(v.x); d[1] = to_tf32(v.y); d[2] = to_tf32(v.z); d[3] = to_tf32(v.w);
        }
        // stage G[k][l] chunk (32 k x 64 l)
#pragma unroll
        for (int r = 0; r < 2; r++) {
            int k = r * 16 + gk;
            float4 v = *(const float4*)(d_gbuf + ((size_t)(b * Hsz + kc * 32 + k)) * Lsz + l0 + gl4 * 4);
            u32* d = &Gs[k * GPITCH + gl4 * 4];
            d[0] = to_tf32(v.x); d[1] = to_tf32(v.y); d[2] = to_tf32(v.z); d[3] = to_tf32(v.w);
        }
        __syncthreads();

#pragma unroll
        for (int k8 = 0; k8 < 4; k8++) {
            int kb = k8 * 8;
            u32 a[2][4];
#pragma unroll
            for (int m = 0; m < 2; m++) {
                int ob = (m << 7) + (w << 4);
                a[m][0] = Ws[(ob + grp) * WPITCH + kb + t4];
                a[m][1] = Ws[(ob + grp + 8) * WPITCH + kb + t4];
                a[m][2] = Ws[(ob + grp) * WPITCH + kb + t4 + 4];
                a[m][3] = Ws[(ob + grp + 8) * WPITCH + kb + t4 + 4];
            }
            u32 bf[8][2];
#pragma unroll
            for (int n = 0; n < 8; n++) {
                bf[n][0] = Gs[(kb + t4) * GPITCH + n * 8 + grp];
                bf[n][1] = Gs[(kb + t4 + 4) * GPITCH + n * 8 + grp];
            }
#pragma unroll
            for (int m = 0; m < 2; m++)
#pragma unroll
                for (int n = 0; n < 8; n++)
                    mma_tf32(acc[m][n], a[m], bf[n]);
        }
        __syncthreads();
    }

    // epilogue: bias + GLU + residual -> sout
    const float* bl = bp + layer * O2;
    int row0 = (w << 4) + grp;         // 'a' row (0..127); gate row = row0 + 128
    float ba0 = bl[row0],       ba1 = bl[row0 + 8];
    float bg0 = bl[row0 + 128], bg1 = bl[row0 + 136];
#pragma unroll
    for (int n = 0; n < 8; n++) {
        int col = n * 8 + 2 * t4;
        size_t g0 = ((size_t)(b * Hsz) + row0) * Lsz + l0 + col;
        float2 r0 = *(const float2*)(d_hact + g0);
        float2 r1 = *(const float2*)(d_hact + g0 + (size_t)8 * Lsz);
        float za0 = acc[0][n][0] + ba0, za1 = acc[0][n][1] + ba0;
        float za2 = acc[0][n][2] + ba1, za3 = acc[0][n][3] + ba1;
        float zg0 = acc[1][n][0] + bg0, zg1 = acc[1][n][1] + bg0;
        float zg2 = acc[1][n][2] + bg1, zg3 = acc[1][n][3] + bg1;
        zg0 = 1.0f / (1.0f + expf(-zg0));
        zg1 = 1.0f / (1.0f + expf(-zg1));
        zg2 = 1.0f / (1.0f + expf(-zg2));
        zg3 = 1.0f / (1.0f + expf(-zg3));
        float o0 = za0 * zg0 + r0.x, o1 = za1 * zg1 + r0.y;
        float o2 = za2 * zg2 + r1.x, o3 = za3 * zg3 + r1.y;
        *(float2*)&sout[row0 * GPITCH + col]       = make_float2(o0, o1);
        *(float2*)&sout[(row0 + 8) * GPITCH + col] = make_float2(o2, o3);
    }
    __syncthreads();

    // LayerNorm over channel dim (128) for each of the 64 l's
    if (t < 64) {
        float sm = 0.0f;
#pragma unroll 8
        for (int hh = 0; hh < Hsz; hh++) sm += sout[hh * GPITCH + t];
        float m = sm * (1.0f / 128.0f);
        float vq = 0.0f;
#pragma unroll 8
        for (int hh = 0; hh < Hsz; hh++) {
            float d = sout[hh * GPITCH + t] - m;
            vq += d * d;
        }
        smu[t] = m;
        srs[t] = rsqrtf(vq * (1.0f / 128.0f) + 1e-5f);
    }
    __syncthreads();

    for (int i = t; i < 2048; i += 256) {
        int hh = i >> 4, jj = (i & 15) << 2;
        float g = lgp[(layer << 7) + hh], bb = lbp[(layer << 7) + hh];
        const float* sp = &sout[hh * GPITCH + jj];
        float4 o;
        o.x = (sp[0] - smu[jj])     * srs[jj]     * g + bb;
        o.y = (sp[1] - smu[jj + 1]) * srs[jj + 1] * g + bb;
        o.z = (sp[2] - smu[jj + 2]) * srs[jj + 2] * g + bb;
        o.w = (sp[3] - smu[jj + 3]) * srs[jj + 3] * g + bb;
        *(float4*)(d_hact + ((size_t)(b * Hsz + hh)) * Lsz + l0 + jj) = o;
    }
}

// ---------------- mean pool over L ----------------
__global__ void pool_kernel() {
    int bh = blockIdx.x;
    int t = threadIdx.x;
    const float4* p = (const float4*)(d_hact + (size_t)bh * Lsz);
    float sm = 0.0f;
    for (int i = t; i < Lsz / 4; i += 128) {
        float4 v = p[i];
        sm += v.x + v.y + v.z + v.w;
    }
#pragma unroll
    for (int o = 16; o; o >>= 1) sm += __shfl_xor_sync(0xffffffffu, sm, o);
    __shared__ float sh[4];
    if ((t & 31) == 0) sh[t >> 5] = sm;
    __syncthreads();
    if (t == 0) d_pool[bh] = (sh[0] + sh[1] + sh[2] + sh[3]) * (1.0f / Lsz);
}

// ---------------- decoder ----------------
__global__ void dec_kernel(const float* __restrict__ dw,
                           const float* __restrict__ db,
                           float* __restrict__ out) {
    int b = blockIdx.x;
    int t = threadIdx.x;
    __shared__ float sp[Hsz];
    sp[t] = d_pool[b * Hsz + t];
    __syncthreads();
    if (t < DOUT) {
        float acc = db[t];
#pragma unroll 8
        for (int h = 0; h < Hsz; h++) acc += sp[h] * dw[t * Hsz + h];
        out[b * DOUT + t] = acc;
    }
}

// ---------------- launch ----------------
extern "C" void kernel_launch(void* const* d_in, const int* in_sizes, int n_in,
                              void* d_out, int out_size) {
    const float* x      = (const float*)d_in[0];
    const float* enc_w  = (const float*)d_in[1];
    const float* enc_b  = (const float*)d_in[2];
    const float* log_dt = (const float*)d_in[3];
    const float* Cp     = (const float*)d_in[4];
    const float* logAre = (const float*)d_in[5];
    const float* Aim    = (const float*)d_in[6];
    const float* Dp     = (const float*)d_in[7];
    const float* out_w  = (const float*)d_in[8];
    const float* out_b  = (const float*)d_in[9];
    const float* ln_g   = (const float*)d_in[10];
    const float* ln_b   = (const float*)d_in[11];
    const float* dec_w  = (const float*)d_in[12];
    const float* dec_b  = (const float*)d_in[13];
    float* out = (float*)d_out;

    prep_kernel<<<64, 256>>>(log_dt, Cp, logAre, Aim);
    enc_kernel<<<(Bsz * Hsz * (Lsz / 4) + 255) / 256, 256>>>(x, enc_w, enc_b);

    for (int layer = 0; layer < NL; layer++) {
        scan_kernel<<<Bsz * Hsz, 64>>>(layer, Dp);
        gluln_kernel<<<dim3(Lsz / 64, Bsz), 256>>>(out_w, out_b, ln_g, ln_b, layer);
    }

    pool_kernel<<<Bsz * Hsz, 128>>>();
    dec_kernel<<<Bsz, 128>>>(dec_w, dec_b, out);
}